// round 16
// baseline (speedup 1.0000x reference)
#include <cuda_runtime.h>
#include <cuda_bf16.h>
#include <math.h>
#include <stdint.h>

#define T_ 1024
#define B_ 8
#define E_ 512
#define H_ 8
#define D_ 64
#define S_ 2048
#define LDA 24
#define LDVB 72
#define KLD 72
#define SBLD 1156

// ---------------- scratch (device globals; no allocations) ----------------
__device__ float g_qin[T_ * B_ * E_];                 // (t,b,e)
__device__ float g_q[B_ * H_ * T_ * D_];              // (b,h,t,d)
__device__ float g_k[B_ * H_ * S_ * D_];              // (b,h,s,d)
__device__ float g_v[B_ * H_ * S_ * D_];              // (b,h,s,d)
__device__ float g_p[(size_t)B_ * H_ * T_ * S_];      // (b,h,t,s)
__device__ float g_attn[T_ * B_ * E_];                // (t,b, h*64+d)

// ---------------- bf16 split + mma helpers ----------------
__device__ __forceinline__ void mma16(float c[4], const uint32_t a[4],
                                      uint32_t b0, uint32_t b1) {
    asm volatile(
        "mma.sync.aligned.m16n8k16.row.col.f32.bf16.bf16.f32 "
        "{%0,%1,%2,%3},{%4,%5,%6,%7},{%8,%9},{%0,%1,%2,%3};"
        : "+f"(c[0]), "+f"(c[1]), "+f"(c[2]), "+f"(c[3])
        : "r"(a[0]), "r"(a[1]), "r"(a[2]), "r"(a[3]), "r"(b0), "r"(b1));
}

__device__ __forceinline__ void lda_frag(uint32_t f[4],
                                         const __nv_bfloat16 (*M)[LDA], int rbase) {
    int lane = threadIdx.x & 31;
    int lm = lane & 7, sel = lane >> 3;
    int row = rbase + lm + (sel & 1) * 8;
    int col = (sel >> 1) * 8;
    uint32_t addr = (uint32_t)__cvta_generic_to_shared(&M[row][col]);
    asm volatile("ldmatrix.sync.aligned.m8n8.x4.shared.b16 {%0,%1,%2,%3}, [%4];"
                 : "=r"(f[0]), "=r"(f[1]), "=r"(f[2]), "=r"(f[3]) : "r"(addr));
}

__device__ __forceinline__ void ldb_frag(uint32_t f[4],
                                         const __nv_bfloat16 (*M)[LDA], int nbase) {
    int lane = threadIdx.x & 31;
    int lm = lane & 7, sel = lane >> 3;
    int row = nbase + lm + (sel >> 1) * 8;
    int col = (sel & 1) * 8;
    uint32_t addr = (uint32_t)__cvta_generic_to_shared(&M[row][col]);
    asm volatile("ldmatrix.sync.aligned.m8n8.x4.shared.b16 {%0,%1,%2,%3}, [%4];"
                 : "=r"(f[0]), "=r"(f[1]), "=r"(f[2]), "=r"(f[3]) : "r"(addr));
}

__device__ __forceinline__ void ldvb_frag(uint32_t f[4],
                                          const __nv_bfloat16 (*M)[LDVB], int nbase) {
    int lane = threadIdx.x & 31;
    int lm = lane & 7, sel = lane >> 3;
    int row = lm + (sel & 1) * 8;
    int col = nbase + (sel >> 1) * 8;
    uint32_t addr = (uint32_t)__cvta_generic_to_shared(&M[row][col]);
    asm volatile("ldmatrix.sync.aligned.m8n8.x4.trans.shared.b16 {%0,%1,%2,%3}, [%4];"
                 : "=r"(f[0]), "=r"(f[1]), "=r"(f[2]), "=r"(f[3]) : "r"(addr));
}

// generic smem-address frag loaders (runtime stride) for the fused kernel
__device__ __forceinline__ void ldm_a16(uint32_t f[4], const __nv_bfloat16* base,
                                        int kk) {
    int lane = threadIdx.x & 31;
    int lm = lane & 7, sel = lane >> 3;
    int row = lm + (sel & 1) * 8;
    int col = kk + (sel >> 1) * 8;
    uint32_t addr = (uint32_t)__cvta_generic_to_shared(base + row * KLD + col);
    asm volatile("ldmatrix.sync.aligned.m8n8.x4.shared.b16 {%0,%1,%2,%3}, [%4];"
                 : "=r"(f[0]), "=r"(f[1]), "=r"(f[2]), "=r"(f[3]) : "r"(addr));
}

__device__ __forceinline__ void ldm_b16(uint32_t f[4], const __nv_bfloat16* base,
                                        int nbase, int kk) {
    int lane = threadIdx.x & 31;
    int lm = lane & 7, sel = lane >> 3;
    int row = nbase + lm + (sel >> 1) * 8;
    int col = kk + (sel & 1) * 8;
    uint32_t addr = (uint32_t)__cvta_generic_to_shared(base + row * KLD + col);
    asm volatile("ldmatrix.sync.aligned.m8n8.x4.shared.b16 {%0,%1,%2,%3}, [%4];"
                 : "=r"(f[0]), "=r"(f[1]), "=r"(f[2]), "=r"(f[3]) : "r"(addr));
}

__device__ __forceinline__ void split2(float a, float b, uint32_t& hu, uint32_t& lu) {
    __nv_bfloat16 h0 = __float2bfloat16(a);
    __nv_bfloat16 l0 = __float2bfloat16(a - __bfloat162float(h0));
    __nv_bfloat16 h1 = __float2bfloat16(b);
    __nv_bfloat16 l1 = __float2bfloat16(b - __bfloat162float(h1));
    hu = (uint32_t)__bfloat16_as_ushort(h0) | ((uint32_t)__bfloat16_as_ushort(h1) << 16);
    lu = (uint32_t)__bfloat16_as_ushort(l0) | ((uint32_t)__bfloat16_as_ushort(l1) << 16);
}

// ---------------- slab staging: load fp32 + convert early ----------------
struct Slab { uint4 h, l; };

__device__ __forceinline__ Slab load_cvt(const float* __restrict__ src, int ld) {
    int r = threadIdx.x >> 1, c = (threadIdx.x & 1) << 3;
    const float* p = src + (size_t)r * ld + c;
    float4 v0 = *(const float4*)p;
    float4 v1 = *(const float4*)(p + 4);
    float v[8] = {v0.x, v0.y, v0.z, v0.w, v1.x, v1.y, v1.z, v1.w};
    uint32_t hu[4], lu[4];
    #pragma unroll
    for (int i = 0; i < 4; i++) split2(v[2*i], v[2*i+1], hu[i], lu[i]);
    Slab s;
    s.h = make_uint4(hu[0], hu[1], hu[2], hu[3]);
    s.l = make_uint4(lu[0], lu[1], lu[2], lu[3]);
    return s;
}

__device__ __forceinline__ void store_slab(const Slab& s,
                                           __nv_bfloat16 (*dh)[LDA],
                                           __nv_bfloat16 (*dl)[LDA]) {
    int r = threadIdx.x >> 1, c = (threadIdx.x & 1) << 3;
    *(uint4*)&dh[r][c] = s.h;
    *(uint4*)&dl[r][c] = s.l;
}

// 128x128 block, 3-pass bf16, one k16 slab already staged
__device__ __forceinline__ void mma_slab3(const __nv_bfloat16 (*Ah)[LDA],
                                          const __nv_bfloat16 (*Al)[LDA],
                                          const __nv_bfloat16 (*Bh)[LDA],
                                          const __nv_bfloat16 (*Bl)[LDA],
                                          float acc[4][4][4]) {
    const int warp = threadIdx.x >> 5;
    const int wm = warp >> 2, wn = warp & 3;
    uint32_t ah[4][4], al[4][4], bh[2][4], bl[2][4];
    #pragma unroll
    for (int mi = 0; mi < 4; mi++) {
        lda_frag(ah[mi], Ah, wm * 64 + mi * 16);
        lda_frag(al[mi], Al, wm * 64 + mi * 16);
    }
    #pragma unroll
    for (int np = 0; np < 2; np++) {
        ldb_frag(bh[np], Bh, wn * 32 + np * 16);
        ldb_frag(bl[np], Bl, wn * 32 + np * 16);
    }
    #pragma unroll
    for (int mi = 0; mi < 4; mi++) {
        #pragma unroll
        for (int ni = 0; ni < 4; ni++) {
            int np = ni >> 1, o = (ni & 1) << 1;
            mma16(acc[mi][ni], ah[mi], bh[np][o], bh[np][o + 1]);
            mma16(acc[mi][ni], ah[mi], bl[np][o], bl[np][o + 1]);
            mma16(acc[mi][ni], al[mi], bh[np][o], bh[np][o + 1]);
        }
    }
}

// ---------------- pipelined 128x128 gemm mainloop (double-buffered) ----------------
__device__ __forceinline__ void gemm_main(const float* __restrict__ A, int lda,
                                          const float* __restrict__ Bsrc, int ldb,
                                          int Kdim,
                                          __nv_bfloat16 (*Ah)[128][LDA],
                                          __nv_bfloat16 (*Al)[128][LDA],
                                          __nv_bfloat16 (*Bh)[128][LDA],
                                          __nv_bfloat16 (*Bl)[128][LDA],
                                          float acc[4][4][4]) {
    Slab sa = load_cvt(A, lda);
    Slab sb = load_cvt(Bsrc, ldb);
    store_slab(sa, Ah[0], Al[0]);
    store_slab(sb, Bh[0], Bl[0]);
    __syncthreads();
    int buf = 0;
    for (int k0 = 16;; k0 += 16) {
        bool more = k0 < Kdim;
        if (more) {
            sa = load_cvt(A + k0, lda);
            sb = load_cvt(Bsrc + k0, ldb);
        }
        mma_slab3(Ah[buf], Al[buf], Bh[buf], Bl[buf], acc);
        if (!more) break;
        buf ^= 1;
        store_slab(sa, Ah[buf], Al[buf]);
        store_slab(sb, Bh[buf], Bl[buf]);
        __syncthreads();
    }
}

// ---------------- q_in = shift(fwd,+1) + shift(bwd,-1), float4 ----------------
__global__ void build_qin_kernel(const float* __restrict__ fwd,
                                 const float* __restrict__ bwd) {
    int i4 = blockIdx.x * blockDim.x + threadIdx.x;
    int idx = i4 << 2;
    int t = idx / (B_ * E_);
    float4 v = make_float4(0.f, 0.f, 0.f, 0.f);
    if (t > 0) {
        float4 a = *(const float4*)(fwd + idx - B_ * E_);
        v.x += a.x; v.y += a.y; v.z += a.z; v.w += a.w;
    }
    if (t < T_ - 1) {
        float4 a = *(const float4*)(bwd + idx + B_ * E_);
        v.x += a.x; v.y += a.y; v.z += a.z; v.w += a.w;
    }
    *(float4*)(g_qin + idx) = v;
}

// ---------------- proj_q ----------------
__global__ __launch_bounds__(256, 2) void proj_q_kernel(const float* __restrict__ W,
                                                        const float* __restrict__ bias) {
    __shared__ __nv_bfloat16 Ah[2][128][LDA], Al[2][128][LDA], Bh[2][128][LDA], Bl[2][128][LDA];
    const int row0 = blockIdx.y * 128;
    const int col0 = blockIdx.x * 128;
    float acc[4][4][4] = {};
    gemm_main(g_qin + (size_t)row0 * E_, E_, W + (size_t)col0 * E_, E_, E_,
              Ah, Al, Bh, Bl, acc);
    const int lane = threadIdx.x & 31, warp = threadIdx.x >> 5;
    const int wm = warp >> 2, wn = warp & 3;
    const int gid = lane >> 2, t4 = lane & 3;
    #pragma unroll
    for (int mi = 0; mi < 4; mi++) {
        #pragma unroll
        for (int ni = 0; ni < 4; ni++) {
            int r = row0 + wm * 64 + mi * 16 + gid;
            int f = col0 + wn * 32 + ni * 8 + 2 * t4;
            int h = f >> 6, d = f & 63;
            float bb0 = bias[f], bb1 = bias[f + 1];
            int t = r >> 3, b = r & 7;
            *(float2*)&g_q[(size_t)(((b << 3) + h) * T_ + t) * D_ + d] =
                make_float2(acc[mi][ni][0] + bb0, acc[mi][ni][1] + bb1);
            *(float2*)&g_q[(size_t)(((b << 3) + h) * T_ + t + 1) * D_ + d] =
                make_float2(acc[mi][ni][2] + bb0, acc[mi][ni][3] + bb1);
        }
    }
}

// ---------------- proj_kv ----------------
__global__ __launch_bounds__(256, 2) void proj_kv_kernel(const float* __restrict__ fwd,
                                                         const float* __restrict__ bwd,
                                                         const float* __restrict__ W,
                                                         const float* __restrict__ bias) {
    __shared__ __nv_bfloat16 Ah[2][128][LDA], Al[2][128][LDA], Bh[2][128][LDA], Bl[2][128][LDA];
    const int row0 = blockIdx.y * 128;
    const int col0 = blockIdx.x * 128;
    const float* A = (row0 < T_ * B_) ? (fwd + (size_t)row0 * E_)
                                      : (bwd + (size_t)(row0 - T_ * B_) * E_);
    float acc[4][4][4] = {};
    gemm_main(A, E_, W + (size_t)(E_ + col0) * E_, E_, E_, Ah, Al, Bh, Bl, acc);
    const int lane = threadIdx.x & 31, warp = threadIdx.x >> 5;
    const int wm = warp >> 2, wn = warp & 3;
    const int gid = lane >> 2, t4 = lane & 3;
    float* dstbase = (col0 < E_) ? g_k : g_v;
    #pragma unroll
    for (int mi = 0; mi < 4; mi++) {
        #pragma unroll
        for (int ni = 0; ni < 4; ni++) {
            int r = row0 + wm * 64 + mi * 16 + gid;
            int f = col0 + wn * 32 + ni * 8 + 2 * t4;
            float bb0 = bias[E_ + f], bb1 = bias[E_ + f + 1];
            int f2 = f & (E_ - 1);
            int h = f2 >> 6, d = f2 & 63;
            int s = r >> 3, b = r & 7;
            *(float2*)&dstbase[((size_t)((b << 3) + h) * S_ + s) * D_ + d] =
                make_float2(acc[mi][ni][0] + bb0, acc[mi][ni][1] + bb1);
            *(float2*)&dstbase[((size_t)((b << 3) + h) * S_ + s + 1) * D_ + d] =
                make_float2(acc[mi][ni][2] + bb0, acc[mi][ni][3] + bb1);
        }
    }
}

// ============ FUSED scores + softmax + avg ============
// block = (t-tile of 16 rows, b); loops h=0..7. 256 threads.
// smem: K double-buffered hi/lo, Q hi/lo, scorebuf [16][SBLD], avgbuf [16][SBLD].
#define FUSED_SMEM (73728 + 4608 + 73984 + 73984 + 64 + 256)

struct KF { uint4 h[4]; uint4 l[4]; };

__device__ __forceinline__ KF load_k16(const float* __restrict__ src) {
    int r = threadIdx.x >> 1, half = (threadIdx.x & 1) * 32;
    const float* p = src + r * 64 + half;
    KF kf;
    #pragma unroll
    for (int i = 0; i < 4; i++) {
        float4 a = *(const float4*)(p + 8 * i);
        float4 b = *(const float4*)(p + 8 * i + 4);
        float vv[8] = {a.x, a.y, a.z, a.w, b.x, b.y, b.z, b.w};
        uint32_t hu[4], lu[4];
        #pragma unroll
        for (int j = 0; j < 4; j++) split2(vv[2*j], vv[2*j+1], hu[j], lu[j]);
        kf.h[i] = make_uint4(hu[0], hu[1], hu[2], hu[3]);
        kf.l[i] = make_uint4(lu[0], lu[1], lu[2], lu[3]);
    }
    return kf;
}

__device__ __forceinline__ void store_k16(const KF& kf,
                                          __nv_bfloat16* Kbh, __nv_bfloat16* Kbl) {
    int r = threadIdx.x >> 1, half = (threadIdx.x & 1) * 32;
    __nv_bfloat16* ph = Kbh + r * KLD + half;
    __nv_bfloat16* pl = Kbl + r * KLD + half;
    #pragma unroll
    for (int i = 0; i < 4; i++) {
        *(uint4*)(ph + 8 * i) = kf.h[i];
        *(uint4*)(pl + 8 * i) = kf.l[i];
    }
}

__global__ __launch_bounds__(256, 1) void fused_sm_kernel(const int* __restrict__ kpm,
                                                          float* __restrict__ avg_out) {
    extern __shared__ char smem[];
    __nv_bfloat16* Kh = (__nv_bfloat16*)smem;            // [2][128*KLD]
    __nv_bfloat16* Kl = Kh + 2 * 128 * KLD;
    __nv_bfloat16* Qh = Kl + 2 * 128 * KLD;              // [16*KLD]
    __nv_bfloat16* Ql = Qh + 16 * KLD;
    float* scorebuf = (float*)(Ql + 16 * KLD);           // [16*SBLD]
    float* avgbuf = scorebuf + 16 * SBLD;                // [16*SBLD]
    float* linv = avgbuf + 16 * SBLD;                    // [16]
    uint32_t* kpmb = (uint32_t*)(linv + 16);             // [64]

    const int tid = threadIdx.x;
    const int t0 = blockIdx.x * 16;
    const int b = blockIdx.y;
    const int i128 = blockIdx.x >> 3;
    const int wid = tid >> 5, lane = tid & 31;
    const int gid = lane >> 2, t4 = lane & 3;
    const int row = tid >> 4, c16 = tid & 15;

    // kpm bitmask (2048 bits)
    if (tid < 64) {
        uint32_t u = 0;
        #pragma unroll 4
        for (int bit = 0; bit < 32; bit++) {
            int s = (tid << 5) | bit;
            if (kpm[b * T_ + (s & (T_ - 1))] != 0) u |= (1u << bit);
        }
        kpmb[tid] = u;
    }
    // zero avgbuf
    for (int i = tid; i < 16 * SBLD / 4; i += 256)
        *(float4*)&avgbuf[i * 4] = make_float4(0.f, 0.f, 0.f, 0.f);
    __syncthreads();

    for (int h = 0; h < H_; h++) {
        const int bh = (b << 3) + h;
        // stage Q 16x64 -> hi/lo
        {
            int r = tid >> 4, c4 = (tid & 15) * 4;
            float4 v = *(const float4*)(g_q + ((size_t)bh * T_ + t0 + r) * D_ + c4);
            uint32_t h0, l0, h1, l1;
            split2(v.x, v.y, h0, l0);
            split2(v.z, v.w, h1, l1);
            *(uint2*)(Qh + r * KLD + c4) = make_uint2(h0, h1);
            *(uint2*)(Ql + r * KLD + c4) = make_uint2(l0, l1);
        }
        const float* Kbase = g_k + (size_t)bh * S_ * D_;
        KF kf = load_k16(Kbase);   // tile n=0 -> j=0 always (0 <= i128)
        store_k16(kf, Kh, Kl);
        __syncthreads();
        for (int n = 0; n < 9; n++) {
            int j = (n <= i128) ? n : n + 7;
            if (n < 8) {
                int j2 = ((n + 1) <= i128) ? (n + 1) : n + 8;
                kf = load_k16(Kbase + (size_t)j2 * 128 * D_);
            }
            int buf = n & 1;
            const __nv_bfloat16* Kbh = Kh + buf * 128 * KLD;
            const __nv_bfloat16* Kbl = Kl + buf * 128 * KLD;
            float acc[2][4] = {};
            #pragma unroll
            for (int kk = 0; kk < 64; kk += 16) {
                uint32_t ah[4], al[4], bhf[4], blf[4];
                ldm_a16(ah, Qh, kk);
                ldm_a16(al, Ql, kk);
                ldm_b16(bhf, Kbh, wid * 16, kk);
                ldm_b16(blf, Kbl, wid * 16, kk);
                #pragma unroll
                for (int ni = 0; ni < 2; ni++) {
                    int o = ni << 1;
                    mma16(acc[ni], ah, bhf[o], bhf[o + 1]);
                    mma16(acc[ni], ah, blf[o], blf[o + 1]);
                    mma16(acc[ni], al, bhf[o], bhf[o + 1]);
                }
            }
            // masked c-frag -> scorebuf
            #pragma unroll
            for (int ni = 0; ni < 2; ni++) {
                int incol = wid * 16 + ni * 8 + 2 * t4;
                int aidx = n * 128 + incol;
                int s = j * 128 + incol;
                bool k0m = (kpmb[s >> 5] >> (s & 31)) & 1;
                bool k1m = (kpmb[(s + 1) >> 5] >> ((s + 1) & 31)) & 1;
                int tr0 = t0 + gid, tr1 = t0 + gid + 8;
                float v00 = (!k0m && ((s < tr0) || (s > tr0 + T_))) ? acc[ni][0] : -1e30f;
                float v01 = (!k1m && ((s + 1 < tr0) || (s + 1 > tr0 + T_))) ? acc[ni][1] : -1e30f;
                float v10 = (!k0m && ((s < tr1) || (s > tr1 + T_))) ? acc[ni][2] : -1e30f;
                float v11 = (!k1m && ((s + 1 < tr1) || (s + 1 > tr1 + T_))) ? acc[ni][3] : -1e30f;
                *(float2*)&scorebuf[gid * SBLD + aidx] = make_float2(v00, v01);
                *(float2*)&scorebuf[(gid + 8) * SBLD + aidx] = make_float2(v10, v11);
            }
            if (n < 8) {
                store_k16(kf, Kh + (buf ^ 1) * 128 * KLD, Kl + (buf ^ 1) * 128 * KLD);
                __syncthreads();
            }
        }
        __syncthreads();
        // softmax: 16 threads per row
        float mx = -1e30f;
        #pragma unroll 8
        for (int i = 0; i < 72; i++)
            mx = fmaxf(mx, scorebuf[row * SBLD + c16 + (i << 4)]);
        #pragma unroll
        for (int o = 8; o; o >>= 1)
            mx = fmaxf(mx, __shfl_xor_sync(0xffffffffu, mx, o));
        float sum = 0.f;
        #pragma unroll 8
        for (int i = 0; i < 72; i++) {
            float* pp = &scorebuf[row * SBLD + c16 + (i << 4)];
            float e = __expf(*pp - mx);
            sum += e;
            *pp = e;
        }
        #pragma unroll
        for (int o = 8; o; o >>= 1)
            sum += __shfl_xor_sync(0xffffffffu, sum, o);
        if (c16 == 0) linv[row] = 1.f / sum;
        __syncthreads();
        // normalize, write p, accumulate avg
        float inv = linv[row];
        float* prow = g_p + ((size_t)bh * T_ + t0 + row) * S_;
        #pragma unroll 4
        for (int k = 0; k < 18; k++) {
            int a = (c16 + (k << 4)) << 2;
            int n = a >> 7;
            int j = n + ((n > i128) ? 7 : 0);
            int s = (j << 7) + (a & 127);
            float4 e4 = *(float4*)&scorebuf[row * SBLD + a];
            float4 p4 = make_float4(e4.x * inv, e4.y * inv, e4.z * inv, e4.w * inv);
            *(float4*)(prow + s) = p4;
            float4* av = (float4*)&avgbuf[row * SBLD + a];
            float4 o = *av;
            o.x += p4.x; o.y += p4.y; o.z += p4.z; o.w += p4.w;
            *av = o;
        }
        __syncthreads();
    }
    // avg epilogue: full 2048 per row (zeros in skipped band)
    float* arow = avg_out + ((size_t)b * T_ + t0 + row) * S_;
    const int bandlo = (i128 << 7) + 128, bandhi = (i128 << 7) + 1024;
    #pragma unroll 4
    for (int k = 0; k < 32; k++) {
        int s = (c16 + (k << 4)) << 2;
        float4 o;
        if (s >= bandlo && s < bandhi) {
            o = make_float4(0.f, 0.f, 0.f, 0.f);
        } else {
            int n = s >> 7;
            if (n > i128) n -= 7;
            int a = (n << 7) + (s & 127);
            float4 v = *(float4*)&avgbuf[row * SBLD + a];
            o = make_float4(v.x * 0.125f, v.y * 0.125f, v.z * 0.125f, v.w * 0.125f);
        }
        *(float4*)(arow + s) = o;
    }
}

// ---------------- attn = p @ v (3-pass bf16, pipelined, skip zero band) ----------------
struct VSlab { uint2 h, l; };

__device__ __forceinline__ VSlab load_cvt_v(const float* __restrict__ V, int k0) {
    int r = threadIdx.x >> 4, c = (threadIdx.x & 15) << 2;
    float4 v = *(const float4*)(V + (size_t)(k0 + r) * D_ + c);
    uint32_t h0, l0, h1, l1;
    split2(v.x, v.y, h0, l0);
    split2(v.z, v.w, h1, l1);
    VSlab s;
    s.h = make_uint2(h0, h1);
    s.l = make_uint2(l0, l1);
    return s;
}

__device__ __forceinline__ void store_vslab(const VSlab& s,
                                            __nv_bfloat16 (*dh)[LDVB],
                                            __nv_bfloat16 (*dl)[LDVB]) {
    int r = threadIdx.x >> 4, c = (threadIdx.x & 15) << 2;
    *(uint2*)&dh[r][c] = s.h;
    *(uint2*)&dl[r][c] = s.l;
}

__global__ __launch_bounds__(256, 2) void attn_kernel() {
    __shared__ __nv_bfloat16 Ph[2][128][LDA], Pl[2][128][LDA];
    __shared__ __nv_bfloat16 Vh[2][16][LDVB], Vl[2][16][LDVB];
    const int t0 = blockIdx.x * 128;
    const int bh = blockIdx.y;
    const float* P = g_p + (size_t)bh * T_ * S_ + (size_t)t0 * S_;
    const float* V = g_v + (size_t)bh * S_ * D_;
    const int tid = threadIdx.x;
    const int lane = tid & 31, warp = tid >> 5;
    const int wm = warp >> 1, wn = warp & 1;
    const int gid = lane >> 2, t4 = lane & 3;
    float acc[2][4][4] = {};
    int k0 = 0;
    Slab ps = load_cvt(P + k0, S_);
    VSlab vs = load_cvt_v(V, k0);
    store_slab(ps, Ph[0], Pl[0]);
    store_vslab(vs, Vh[0], Vl[0]);
    __syncthreads();
    int buf = 0;
    while (true) {
        int k1 = (k0 + 16 == t0 + 128) ? t0 + 1024 : k0 + 16;
        bool more = k1 < S_;
        if (more) {
            ps = load_cvt(P + k1, S_);
            vs = load_cvt_v(V, k1);
        }
        {
            uint32_t ah[2][4], al[2][4], bh2[2][4], bl2[2][4];
            #pragma unroll
            for (int mi = 0; mi < 2; mi++) {
                lda_frag(ah[mi], Ph[buf], wm * 32 + mi * 16);
                lda_frag(al[mi], Pl[buf], wm * 32 + mi * 16);
            }
            #pragma unroll
            for (int np = 0; np < 2; np++) {
                ldvb_frag(bh2[np], Vh[buf], wn * 32 + np * 16);
                ldvb_frag(bl2[np], Vl[buf], wn * 32 + np * 16);
            }
            #pragma unroll
            for (int mi = 0; mi < 2; mi++) {
                #pragma unroll
                for (int ni = 0; ni < 4; ni++) {
                    int np = ni >> 1, o = (ni & 1) << 1;
                    mma16(acc[mi][ni], ah[mi], bh2[np][o], bh2[np][o + 1]);
                    mma16(acc[mi][ni], ah[mi], bl2[np][o], bl2[np][o + 1]);
                    mma16(acc[mi][ni], al[mi], bh2[np][o], bh2[np][o + 1]);
                }
            }
        }
        if (!more) break;
        buf ^= 1;
        store_slab(ps, Ph[buf], Pl[buf]);
        store_vslab(vs, Vh[buf], Vl[buf]);
        __syncthreads();
        k0 = k1;
    }
    const int b = bh >> 3, h = bh & 7;
    #pragma unroll
    for (int mi = 0; mi < 2; mi++) {
        #pragma unroll
        for (int ni = 0; ni < 4; ni++) {
            int t = t0 + wm * 32 + mi * 16 + gid;
            int d = wn * 32 + ni * 8 + 2 * t4;
            *(float2*)&g_attn[(size_t)((t << 3) + b) * E_ + (h << 6) + d] =
                make_float2(acc[mi][ni][0], acc[mi][ni][1]);
            *(float2*)&g_attn[(size_t)(((t + 8) << 3) + b) * E_ + (h << 6) + d] =
                make_float2(acc[mi][ni][2], acc[mi][ni][3]);
        }
    }
}

// ---------------- out = attn @ out_w^T + out_b (3-pass bf16) ----------------
__global__ __launch_bounds__(256, 2) void out_proj_kernel(const float* __restrict__ W,
                                                          const float* __restrict__ bias,
                                                          float* __restrict__ out) {
    __shared__ __nv_bfloat16 Ah[2][128][LDA], Al[2][128][LDA], Bh[2][128][LDA], Bl[2][128][LDA];
    const int row0 = blockIdx.y * 128;
    const int col0 = blockIdx.x * 128;
    float acc[4][4][4] = {};
    gemm_main(g_attn + (size_t)row0 * E_, E_, W + (size_t)col0 * E_, E_, E_,
              Ah, Al, Bh, Bl, acc);
    const int lane = threadIdx.x & 31, warp = threadIdx.x >> 5;
    const int wm = warp >> 2, wn = warp & 3;
    const int gid = lane >> 2, t4 = lane & 3;
    #pragma unroll
    for (int mi = 0; mi < 4; mi++) {
        #pragma unroll
        for (int ni = 0; ni < 4; ni++) {
            int r = row0 + wm * 64 + mi * 16 + gid;
            int f = col0 + wn * 32 + ni * 8 + 2 * t4;
            float bb0 = bias[f], bb1 = bias[f + 1];
            *(float2*)&out[(size_t)r * E_ + f] =
                make_float2(acc[mi][ni][0] + bb0, acc[mi][ni][1] + bb1);
            *(float2*)&out[(size_t)(r + 8) * E_ + f] =
                make_float2(acc[mi][ni][2] + bb0, acc[mi][ni][3] + bb1);
        }
    }
}

// ---------------- launch ----------------
extern "C" void kernel_launch(void* const* d_in, const int* in_sizes, int n_in,
                              void* d_out, int out_size) {
    const float* fwd  = (const float*)d_in[0];
    const float* bwd  = (const float*)d_in[1];
    const int*   kpm  = (const int*)d_in[2];
    const float* W    = (const float*)d_in[3];   // (3E, E)
    const float* bias = (const float*)d_in[4];   // (3E,)
    const float* outw = (const float*)d_in[5];   // (E, E)
    const float* outb = (const float*)d_in[6];   // (E,)
    float* out = (float*)d_out;                       // (T,B,E)
    float* avg = out + (size_t)T_ * B_ * E_;          // (B,T,S)

    cudaFuncSetAttribute(fused_sm_kernel,
                         cudaFuncAttributeMaxDynamicSharedMemorySize, FUSED_SMEM);

    build_qin_kernel<<<(T_ * B_ * E_) / 1024, 256>>>(fwd, bwd);
    proj_q_kernel<<<dim3(E_ / 128, (T_ * B_) / 128), 256>>>(W, bias);
    proj_kv_kernel<<<dim3((2 * E_) / 128, (S_ * B_) / 128), 256>>>(fwd, bwd, W, bias);
    fused_sm_kernel<<<dim3(T_ / 16, B_), 256, FUSED_SMEM>>>(kpm, avg);
    attn_kernel<<<dim3(T_ / 128, B_ * H_), 256>>>();
    out_proj_kernel<<<dim3(E_ / 128, (T_ * B_) / 128), 256>>>(outw, outb, out);
}

// round 17
// speedup vs baseline: 1.6128x; 1.6128x over previous
#include <cuda_runtime.h>
#include <cuda_bf16.h>
#include <math.h>
#include <stdint.h>

#define T_ 1024
#define B_ 8
#define E_ 512
#define H_ 8
#define D_ 64
#define S_ 2048
#define LDA 24
#define LDVB 72
#define KLD 72

// ---------------- scratch (device globals; no allocations) ----------------
__device__ float g_qin[T_ * B_ * E_];                 // (t,b,e)
__device__ float g_q[B_ * H_ * T_ * D_];              // (b,h,t,d)
__device__ float g_k[B_ * H_ * S_ * D_];              // (b,h,s,d)
__device__ float g_v[B_ * H_ * S_ * D_];              // (b,h,s,d)
__device__ float g_p[(size_t)B_ * H_ * T_ * S_];      // (b,h,t,s)
__device__ float g_attn[T_ * B_ * E_];                // (t,b, h*64+d)

// ---------------- bf16 split + mma helpers ----------------
__device__ __forceinline__ void mma16(float c[4], const uint32_t a[4],
                                      uint32_t b0, uint32_t b1) {
    asm volatile(
        "mma.sync.aligned.m16n8k16.row.col.f32.bf16.bf16.f32 "
        "{%0,%1,%2,%3},{%4,%5,%6,%7},{%8,%9},{%0,%1,%2,%3};"
        : "+f"(c[0]), "+f"(c[1]), "+f"(c[2]), "+f"(c[3])
        : "r"(a[0]), "r"(a[1]), "r"(a[2]), "r"(a[3]), "r"(b0), "r"(b1));
}

__device__ __forceinline__ void lda_frag(uint32_t f[4],
                                         const __nv_bfloat16 (*M)[LDA], int rbase) {
    int lane = threadIdx.x & 31;
    int lm = lane & 7, sel = lane >> 3;
    int row = rbase + lm + (sel & 1) * 8;
    int col = (sel >> 1) * 8;
    uint32_t addr = (uint32_t)__cvta_generic_to_shared(&M[row][col]);
    asm volatile("ldmatrix.sync.aligned.m8n8.x4.shared.b16 {%0,%1,%2,%3}, [%4];"
                 : "=r"(f[0]), "=r"(f[1]), "=r"(f[2]), "=r"(f[3]) : "r"(addr));
}

__device__ __forceinline__ void ldb_frag(uint32_t f[4],
                                         const __nv_bfloat16 (*M)[LDA], int nbase) {
    int lane = threadIdx.x & 31;
    int lm = lane & 7, sel = lane >> 3;
    int row = nbase + lm + (sel >> 1) * 8;
    int col = (sel & 1) * 8;
    uint32_t addr = (uint32_t)__cvta_generic_to_shared(&M[row][col]);
    asm volatile("ldmatrix.sync.aligned.m8n8.x4.shared.b16 {%0,%1,%2,%3}, [%4];"
                 : "=r"(f[0]), "=r"(f[1]), "=r"(f[2]), "=r"(f[3]) : "r"(addr));
}

__device__ __forceinline__ void ldvb_frag(uint32_t f[4],
                                          const __nv_bfloat16 (*M)[LDVB], int nbase) {
    int lane = threadIdx.x & 31;
    int lm = lane & 7, sel = lane >> 3;
    int row = lm + (sel & 1) * 8;
    int col = nbase + (sel >> 1) * 8;
    uint32_t addr = (uint32_t)__cvta_generic_to_shared(&M[row][col]);
    asm volatile("ldmatrix.sync.aligned.m8n8.x4.trans.shared.b16 {%0,%1,%2,%3}, [%4];"
                 : "=r"(f[0]), "=r"(f[1]), "=r"(f[2]), "=r"(f[3]) : "r"(addr));
}

// KLD-stride frag loaders (for scores kernel, whole-K staging)
__device__ __forceinline__ void ldmK_a(uint32_t f[4], const __nv_bfloat16* base,
                                       int rbase, int kk) {
    int lane = threadIdx.x & 31;
    int lm = lane & 7, sel = lane >> 3;
    int row = rbase + lm + (sel & 1) * 8;
    int col = kk + (sel >> 1) * 8;
    uint32_t addr = (uint32_t)__cvta_generic_to_shared(base + row * KLD + col);
    asm volatile("ldmatrix.sync.aligned.m8n8.x4.shared.b16 {%0,%1,%2,%3}, [%4];"
                 : "=r"(f[0]), "=r"(f[1]), "=r"(f[2]), "=r"(f[3]) : "r"(addr));
}

__device__ __forceinline__ void ldmK_b(uint32_t f[4], const __nv_bfloat16* base,
                                       int nbase, int kk) {
    int lane = threadIdx.x & 31;
    int lm = lane & 7, sel = lane >> 3;
    int row = nbase + lm + (sel >> 1) * 8;
    int col = kk + (sel & 1) * 8;
    uint32_t addr = (uint32_t)__cvta_generic_to_shared(base + row * KLD + col);
    asm volatile("ldmatrix.sync.aligned.m8n8.x4.shared.b16 {%0,%1,%2,%3}, [%4];"
                 : "=r"(f[0]), "=r"(f[1]), "=r"(f[2]), "=r"(f[3]) : "r"(addr));
}

__device__ __forceinline__ void split2(float a, float b, uint32_t& hu, uint32_t& lu) {
    __nv_bfloat16 h0 = __float2bfloat16(a);
    __nv_bfloat16 l0 = __float2bfloat16(a - __bfloat162float(h0));
    __nv_bfloat16 h1 = __float2bfloat16(b);
    __nv_bfloat16 l1 = __float2bfloat16(b - __bfloat162float(h1));
    hu = (uint32_t)__bfloat16_as_ushort(h0) | ((uint32_t)__bfloat16_as_ushort(h1) << 16);
    lu = (uint32_t)__bfloat16_as_ushort(l0) | ((uint32_t)__bfloat16_as_ushort(l1) << 16);
}

// ---------------- slab staging: load fp32 + convert early ----------------
struct Slab { uint4 h, l; };

__device__ __forceinline__ Slab load_cvt(const float* __restrict__ src, int ld) {
    int r = threadIdx.x >> 1, c = (threadIdx.x & 1) << 3;
    const float* p = src + (size_t)r * ld + c;
    float4 v0 = *(const float4*)p;
    float4 v1 = *(const float4*)(p + 4);
    float v[8] = {v0.x, v0.y, v0.z, v0.w, v1.x, v1.y, v1.z, v1.w};
    uint32_t hu[4], lu[4];
    #pragma unroll
    for (int i = 0; i < 4; i++) split2(v[2*i], v[2*i+1], hu[i], lu[i]);
    Slab s;
    s.h = make_uint4(hu[0], hu[1], hu[2], hu[3]);
    s.l = make_uint4(lu[0], lu[1], lu[2], lu[3]);
    return s;
}

__device__ __forceinline__ void store_slab(const Slab& s,
                                           __nv_bfloat16 (*dh)[LDA],
                                           __nv_bfloat16 (*dl)[LDA]) {
    int r = threadIdx.x >> 1, c = (threadIdx.x & 1) << 3;
    *(uint4*)&dh[r][c] = s.h;
    *(uint4*)&dl[r][c] = s.l;
}

// 128x128 block, 3-pass bf16, one k16 slab already staged
__device__ __forceinline__ void mma_slab3(const __nv_bfloat16 (*Ah)[LDA],
                                          const __nv_bfloat16 (*Al)[LDA],
                                          const __nv_bfloat16 (*Bh)[LDA],
                                          const __nv_bfloat16 (*Bl)[LDA],
                                          float acc[4][4][4]) {
    const int warp = threadIdx.x >> 5;
    const int wm = warp >> 2, wn = warp & 3;
    uint32_t ah[4][4], al[4][4], bh[2][4], bl[2][4];
    #pragma unroll
    for (int mi = 0; mi < 4; mi++) {
        lda_frag(ah[mi], Ah, wm * 64 + mi * 16);
        lda_frag(al[mi], Al, wm * 64 + mi * 16);
    }
    #pragma unroll
    for (int np = 0; np < 2; np++) {
        ldb_frag(bh[np], Bh, wn * 32 + np * 16);
        ldb_frag(bl[np], Bl, wn * 32 + np * 16);
    }
    #pragma unroll
    for (int mi = 0; mi < 4; mi++) {
        #pragma unroll
        for (int ni = 0; ni < 4; ni++) {
            int np = ni >> 1, o = (ni & 1) << 1;
            mma16(acc[mi][ni], ah[mi], bh[np][o], bh[np][o + 1]);
            mma16(acc[mi][ni], ah[mi], bl[np][o], bl[np][o + 1]);
            mma16(acc[mi][ni], al[mi], bh[np][o], bh[np][o + 1]);
        }
    }
}

// ---------------- pipelined 128x128 gemm mainloop (double-buffered) ----------------
__device__ __forceinline__ void gemm_main(const float* __restrict__ A, int lda,
                                          const float* __restrict__ Bsrc, int ldb,
                                          int Kdim,
                                          __nv_bfloat16 (*Ah)[128][LDA],
                                          __nv_bfloat16 (*Al)[128][LDA],
                                          __nv_bfloat16 (*Bh)[128][LDA],
                                          __nv_bfloat16 (*Bl)[128][LDA],
                                          float acc[4][4][4]) {
    Slab sa = load_cvt(A, lda);
    Slab sb = load_cvt(Bsrc, ldb);
    store_slab(sa, Ah[0], Al[0]);
    store_slab(sb, Bh[0], Bl[0]);
    __syncthreads();
    int buf = 0;
    for (int k0 = 16;; k0 += 16) {
        bool more = k0 < Kdim;
        if (more) {
            sa = load_cvt(A + k0, lda);
            sb = load_cvt(Bsrc + k0, ldb);
        }
        mma_slab3(Ah[buf], Al[buf], Bh[buf], Bl[buf], acc);
        if (!more) break;
        buf ^= 1;
        store_slab(sa, Ah[buf], Al[buf]);
        store_slab(sb, Bh[buf], Bl[buf]);
        __syncthreads();
    }
}

// ---------------- q_in = shift(fwd,+1) + shift(bwd,-1), float4 ----------------
__global__ void build_qin_kernel(const float* __restrict__ fwd,
                                 const float* __restrict__ bwd) {
    int i4 = blockIdx.x * blockDim.x + threadIdx.x;
    int idx = i4 << 2;
    int t = idx / (B_ * E_);
    float4 v = make_float4(0.f, 0.f, 0.f, 0.f);
    if (t > 0) {
        float4 a = *(const float4*)(fwd + idx - B_ * E_);
        v.x += a.x; v.y += a.y; v.z += a.z; v.w += a.w;
    }
    if (t < T_ - 1) {
        float4 a = *(const float4*)(bwd + idx + B_ * E_);
        v.x += a.x; v.y += a.y; v.z += a.z; v.w += a.w;
    }
    *(float4*)(g_qin + idx) = v;
}

// ---------------- proj_q ----------------
__global__ __launch_bounds__(256, 2) void proj_q_kernel(const float* __restrict__ W,
                                                        const float* __restrict__ bias) {
    __shared__ __nv_bfloat16 Ah[2][128][LDA], Al[2][128][LDA], Bh[2][128][LDA], Bl[2][128][LDA];
    const int row0 = blockIdx.y * 128;
    const int col0 = blockIdx.x * 128;
    float acc[4][4][4] = {};
    gemm_main(g_qin + (size_t)row0 * E_, E_, W + (size_t)col0 * E_, E_, E_,
              Ah, Al, Bh, Bl, acc);
    const int lane = threadIdx.x & 31, warp = threadIdx.x >> 5;
    const int wm = warp >> 2, wn = warp & 3;
    const int gid = lane >> 2, t4 = lane & 3;
    #pragma unroll
    for (int mi = 0; mi < 4; mi++) {
        #pragma unroll
        for (int ni = 0; ni < 4; ni++) {
            int r = row0 + wm * 64 + mi * 16 + gid;
            int f = col0 + wn * 32 + ni * 8 + 2 * t4;
            int h = f >> 6, d = f & 63;
            float bb0 = bias[f], bb1 = bias[f + 1];
            int t = r >> 3, b = r & 7;
            *(float2*)&g_q[(size_t)(((b << 3) + h) * T_ + t) * D_ + d] =
                make_float2(acc[mi][ni][0] + bb0, acc[mi][ni][1] + bb1);
            *(float2*)&g_q[(size_t)(((b << 3) + h) * T_ + t + 1) * D_ + d] =
                make_float2(acc[mi][ni][2] + bb0, acc[mi][ni][3] + bb1);
        }
    }
}

// ---------------- proj_kv ----------------
__global__ __launch_bounds__(256, 2) void proj_kv_kernel(const float* __restrict__ fwd,
                                                         const float* __restrict__ bwd,
                                                         const float* __restrict__ W,
                                                         const float* __restrict__ bias) {
    __shared__ __nv_bfloat16 Ah[2][128][LDA], Al[2][128][LDA], Bh[2][128][LDA], Bl[2][128][LDA];
    const int row0 = blockIdx.y * 128;
    const int col0 = blockIdx.x * 128;
    const float* A = (row0 < T_ * B_) ? (fwd + (size_t)row0 * E_)
                                      : (bwd + (size_t)(row0 - T_ * B_) * E_);
    float acc[4][4][4] = {};
    gemm_main(A, E_, W + (size_t)(E_ + col0) * E_, E_, E_, Ah, Al, Bh, Bl, acc);
    const int lane = threadIdx.x & 31, warp = threadIdx.x >> 5;
    const int wm = warp >> 2, wn = warp & 3;
    const int gid = lane >> 2, t4 = lane & 3;
    float* dstbase = (col0 < E_) ? g_k : g_v;
    #pragma unroll
    for (int mi = 0; mi < 4; mi++) {
        #pragma unroll
        for (int ni = 0; ni < 4; ni++) {
            int r = row0 + wm * 64 + mi * 16 + gid;
            int f = col0 + wn * 32 + ni * 8 + 2 * t4;
            float bb0 = bias[E_ + f], bb1 = bias[E_ + f + 1];
            int f2 = f & (E_ - 1);
            int h = f2 >> 6, d = f2 & 63;
            int s = r >> 3, b = r & 7;
            *(float2*)&dstbase[((size_t)((b << 3) + h) * S_ + s) * D_ + d] =
                make_float2(acc[mi][ni][0] + bb0, acc[mi][ni][1] + bb1);
            *(float2*)&dstbase[((size_t)((b << 3) + h) * S_ + s + 1) * D_ + d] =
                make_float2(acc[mi][ni][2] + bb0, acc[mi][ni][3] + bb1);
        }
    }
}

// ---------------- scores: whole-K single-stage staging, no pipeline ----------------
// dynamic smem: Qh, Ql, Kh, Kl each [128][KLD] bf16 = 73728 bytes total
#define SC_SMEM (4 * 128 * KLD * 2)

__global__ __launch_bounds__(256, 2) void scores_kernel() {
    extern __shared__ __nv_bfloat16 smsc[];
    __nv_bfloat16* Qh = smsc;
    __nv_bfloat16* Ql = Qh + 128 * KLD;
    __nv_bfloat16* Kh = Ql + 128 * KLD;
    __nv_bfloat16* Kl = Kh + 128 * KLD;
    const int bh = blockIdx.z;
    const int it = blockIdx.y;
    const int n = blockIdx.x;
    const int j = (n <= it) ? n : n + 7;
    const int t0 = it * 128;
    const int s0 = j * 128;
    const int tid = threadIdx.x;
    const int r = tid >> 1, c0 = (tid & 1) * 32;
    // stage Q (128x64) hi/lo
    {
        const float* src = g_q + ((size_t)bh * T_ + t0 + r) * D_ + c0;
        float4 v[8];
        #pragma unroll
        for (int i = 0; i < 8; i++) v[i] = *(const float4*)(src + 4 * i);
        #pragma unroll
        for (int i = 0; i < 4; i++) {
            uint32_t h0, l0, h1, l1;
            split2(v[2*i].x, v[2*i].y, h0, l0);
            split2(v[2*i].z, v[2*i].w, h1, l1);
            uint32_t h2, l2, h3, l3;
            split2(v[2*i+1].x, v[2*i+1].y, h2, l2);
            split2(v[2*i+1].z, v[2*i+1].w, h3, l3);
            *(uint4*)(Qh + r * KLD + c0 + 8 * i) = make_uint4(h0, h1, h2, h3);
            *(uint4*)(Ql + r * KLD + c0 + 8 * i) = make_uint4(l0, l1, l2, l3);
        }
    }
    // stage K (128x64) hi/lo
    {
        const float* src = g_k + ((size_t)bh * S_ + s0 + r) * D_ + c0;
        float4 v[8];
        #pragma unroll
        for (int i = 0; i < 8; i++) v[i] = *(const float4*)(src + 4 * i);
        #pragma unroll
        for (int i = 0; i < 4; i++) {
            uint32_t h0, l0, h1, l1;
            split2(v[2*i].x, v[2*i].y, h0, l0);
            split2(v[2*i].z, v[2*i].w, h1, l1);
            uint32_t h2, l2, h3, l3;
            split2(v[2*i+1].x, v[2*i+1].y, h2, l2);
            split2(v[2*i+1].z, v[2*i+1].w, h3, l3);
            *(uint4*)(Kh + r * KLD + c0 + 8 * i) = make_uint4(h0, h1, h2, h3);
            *(uint4*)(Kl + r * KLD + c0 + 8 * i) = make_uint4(l0, l1, l2, l3);
        }
    }
    __syncthreads();
    const int lane = tid & 31, warp = tid >> 5;
    const int wm = warp >> 2, wn = warp & 3;
    const int gid = lane >> 2, t4 = lane & 3;
    float acc[4][4][4] = {};
    #pragma unroll
    for (int kk = 0; kk < 64; kk += 16) {
        uint32_t ah[4][4], al[4][4], bhf[2][4], blf[2][4];
        #pragma unroll
        for (int mi = 0; mi < 4; mi++) {
            ldmK_a(ah[mi], Qh, wm * 64 + mi * 16, kk);
            ldmK_a(al[mi], Ql, wm * 64 + mi * 16, kk);
        }
        #pragma unroll
        for (int np = 0; np < 2; np++) {
            ldmK_b(bhf[np], Kh, wn * 32 + np * 16, kk);
            ldmK_b(blf[np], Kl, wn * 32 + np * 16, kk);
        }
        #pragma unroll
        for (int mi = 0; mi < 4; mi++) {
            #pragma unroll
            for (int ni = 0; ni < 4; ni++) {
                int np = ni >> 1, o = (ni & 1) << 1;
                mma16(acc[mi][ni], ah[mi], bhf[np][o], bhf[np][o + 1]);
                mma16(acc[mi][ni], ah[mi], blf[np][o], blf[np][o + 1]);
                mma16(acc[mi][ni], al[mi], bhf[np][o], bhf[np][o + 1]);
            }
        }
    }
    float* P = g_p + (size_t)bh * T_ * S_;
    #pragma unroll
    for (int mi = 0; mi < 4; mi++) {
        #pragma unroll
        for (int ni = 0; ni < 4; ni++) {
            int rr = t0 + wm * 64 + mi * 16 + gid;
            int cc = s0 + wn * 32 + ni * 8 + 2 * t4;
            *(float2*)&P[(size_t)rr * S_ + cc] = make_float2(acc[mi][ni][0], acc[mi][ni][1]);
            *(float2*)&P[(size_t)(rr + 8) * S_ + cc] = make_float2(acc[mi][ni][2], acc[mi][ni][3]);
        }
    }
}

// ---------------- softmax per (b,t) + head-mean; 4-head batched loads ----------------
__device__ __forceinline__ float blk_reduce(float v, bool is_max, float* red) {
    #pragma unroll
    for (int o = 16; o; o >>= 1) {
        float w = __shfl_xor_sync(0xffffffffu, v, o);
        v = is_max ? fmaxf(v, w) : v + w;
    }
    if ((threadIdx.x & 31) == 0) red[threadIdx.x >> 5] = v;
    __syncthreads();
    if (threadIdx.x < 32) {
        float x = (threadIdx.x < 8) ? red[threadIdx.x] : (is_max ? -1e30f : 0.f);
        #pragma unroll
        for (int o = 4; o; o >>= 1) {
            float w = __shfl_xor_sync(0xffffffffu, x, o);
            x = is_max ? fmaxf(x, w) : x + w;
        }
        if (threadIdx.x == 0) red[0] = x;
    }
    __syncthreads();
    float r = red[0];
    __syncthreads();
    return r;
}

__global__ void softmax_avg_kernel(const int* __restrict__ kpm,
                                   float* __restrict__ avg_out) {
    __shared__ float red[32];
    const int bt = blockIdx.x;
    const int b = bt >> 10;
    const int t = bt & (T_ - 1);
    const int t0 = t & ~127;
    const int tid = threadIdx.x;
    bool msk[2][4];
    bool wr[2], band[2];
    #pragma unroll
    for (int i = 0; i < 2; i++) {
        int s4 = (tid << 2) + (i << 10);
        wr[i] = (s4 < t0 + 128) || (s4 >= t0 + 1024);
        band[i] = (s4 >= t) && (s4 + 3 <= t + T_);
        #pragma unroll
        for (int e = 0; e < 4; e++) {
            int s = s4 + e;
            msk[i][e] = (s >= t && s <= t + T_) || (kpm[b * T_ + (s & (T_ - 1))] != 0);
        }
    }
    float avg[2][4] = {};
    for (int hb = 0; hb < H_; hb += 4) {
        float vreg[4][2][4];
        // batch-issue loads for 4 heads (MLP 8)
        #pragma unroll
        for (int hh = 0; hh < 4; hh++) {
            const float* row = g_p + ((size_t)(((b << 3) + hb + hh) * T_ + t)) * S_;
            #pragma unroll
            for (int i = 0; i < 2; i++) {
                int s4 = (tid << 2) + (i << 10);
                float4 v = band[i] ? make_float4(0.f, 0.f, 0.f, 0.f)
                                   : *(const float4*)(row + s4);
                vreg[hh][i][0] = v.x; vreg[hh][i][1] = v.y;
                vreg[hh][i][2] = v.z; vreg[hh][i][3] = v.w;
            }
        }
        #pragma unroll
        for (int hh = 0; hh < 4; hh++) {
            float m = -1e30f;
            #pragma unroll
            for (int i = 0; i < 2; i++)
                #pragma unroll
                for (int e = 0; e < 4; e++) {
                    float x = msk[i][e] ? -1e30f : vreg[hh][i][e];
                    vreg[hh][i][e] = x;
                    m = fmaxf(m, x);
                }
            m = blk_reduce(m, true, red);
            float sum = 0.f;
            #pragma unroll
            for (int i = 0; i < 2; i++)
                #pragma unroll
                for (int e = 0; e < 4; e++) {
                    if (!msk[i][e]) { vreg[hh][i][e] = __expf(vreg[hh][i][e] - m); sum += vreg[hh][i][e]; }
                    else vreg[hh][i][e] = 0.f;
                }
            sum = blk_reduce(sum, false, red);
            float inv = 1.f / sum;
            float* row = g_p + ((size_t)(((b << 3) + hb + hh) * T_ + t)) * S_;
            #pragma unroll
            for (int i = 0; i < 2; i++) {
                int s4 = (tid << 2) + (i << 10);
                float p0 = vreg[hh][i][0] * inv, p1 = vreg[hh][i][1] * inv;
                float p2 = vreg[hh][i][2] * inv, p3 = vreg[hh][i][3] * inv;
                if (wr[i])
                    *(float4*)(row + s4) = make_float4(p0, p1, p2, p3);
                avg[i][0] += p0; avg[i][1] += p1; avg[i][2] += p2; avg[i][3] += p3;
            }
        }
    }
    size_t o = (size_t)bt * S_;
    #pragma unroll
    for (int i = 0; i < 2; i++) {
        int s4 = (tid << 2) + (i << 10);
        *(float4*)(avg_out + o + s4) = make_float4(avg[i][0] * 0.125f, avg[i][1] * 0.125f,
                                                   avg[i][2] * 0.125f, avg[i][3] * 0.125f);
    }
}

// ---------------- attn = p @ v (3-pass bf16, pipelined, skip zero band) ----------------
struct VSlab { uint2 h, l; };

__device__ __forceinline__ VSlab load_cvt_v(const float* __restrict__ V, int k0) {
    int r = threadIdx.x >> 4, c = (threadIdx.x & 15) << 2;
    float4 v = *(const float4*)(V + (size_t)(k0 + r) * D_ + c);
    uint32_t h0, l0, h1, l1;
    split2(v.x, v.y, h0, l0);
    split2(v.z, v.w, h1, l1);
    VSlab s;
    s.h = make_uint2(h0, h1);
    s.l = make_uint2(l0, l1);
    return s;
}

__device__ __forceinline__ void store_vslab(const VSlab& s,
                                            __nv_bfloat16 (*dh)[LDVB],
                                            __nv_bfloat16 (*dl)[LDVB]) {
    int r = threadIdx.x >> 4, c = (threadIdx.x & 15) << 2;
    *(uint2*)&dh[r][c] = s.h;
    *(uint2*)&dl[r][c] = s.l;
}

__global__ __launch_bounds__(256, 2) void attn_kernel() {
    __shared__ __nv_bfloat16 Ph[2][128][LDA], Pl[2][128][LDA];
    __shared__ __nv_bfloat16 Vh[2][16][LDVB], Vl[2][16][LDVB];
    const int t0 = blockIdx.x * 128;
    const int bh = blockIdx.y;
    const float* P = g_p + (size_t)bh * T_ * S_ + (size_t)t0 * S_;
    const float* V = g_v + (size_t)bh * S_ * D_;
    const int tid = threadIdx.x;
    const int lane = tid & 31, warp = tid >> 5;
    const int wm = warp >> 1, wn = warp & 1;
    const int gid = lane >> 2, t4 = lane & 3;
    float acc[2][4][4] = {};
    int k0 = 0;
    Slab ps = load_cvt(P + k0, S_);
    VSlab vs = load_cvt_v(V, k0);
    store_slab(ps, Ph[0], Pl[0]);
    store_vslab(vs, Vh[0], Vl[0]);
    __syncthreads();
    int buf = 0;
    while (true) {
        int k1 = (k0 + 16 == t0 + 128) ? t0 + 1024 : k0 + 16;
        bool more = k1 < S_;
        if (more) {
            ps = load_cvt(P + k1, S_);
            vs = load_cvt_v(V, k1);
        }
        {
            uint32_t ah[2][4], al[2][4], bh2[2][4], bl2[2][4];
            #pragma unroll
            for (int mi = 0; mi < 2; mi++) {
                lda_frag(ah[mi], Ph[buf], wm * 32 + mi * 16);
                lda_frag(al[mi], Pl[buf], wm * 32 + mi * 16);
            }
            #pragma unroll
            for (int np = 0; np < 2; np++) {
                ldvb_frag(bh2[np], Vh[buf], wn * 32 + np * 16);
                ldvb_frag(bl2[np], Vl[buf], wn * 32 + np * 16);
            }
            #pragma unroll
            for (int mi = 0; mi < 2; mi++) {
                #pragma unroll
                for (int ni = 0; ni < 4; ni++) {
                    int np = ni >> 1, o = (ni & 1) << 1;
                    mma16(acc[mi][ni], ah[mi], bh2[np][o], bh2[np][o + 1]);
                    mma16(acc[mi][ni], ah[mi], bl2[np][o], bl2[np][o + 1]);
                    mma16(acc[mi][ni], al[mi], bh2[np][o], bh2[np][o + 1]);
                }
            }
        }
        if (!more) break;
        buf ^= 1;
        store_slab(ps, Ph[buf], Pl[buf]);
        store_vslab(vs, Vh[buf], Vl[buf]);
        __syncthreads();
        k0 = k1;
    }
    const int b = bh >> 3, h = bh & 7;
    #pragma unroll
    for (int mi = 0; mi < 2; mi++) {
        #pragma unroll
        for (int ni = 0; ni < 4; ni++) {
            int t = t0 + wm * 32 + mi * 16 + gid;
            int d = wn * 32 + ni * 8 + 2 * t4;
            *(float2*)&g_attn[(size_t)((t << 3) + b) * E_ + (h << 6) + d] =
                make_float2(acc[mi][ni][0], acc[mi][ni][1]);
            *(float2*)&g_attn[(size_t)(((t + 8) << 3) + b) * E_ + (h << 6) + d] =
                make_float2(acc[mi][ni][2], acc[mi][ni][3]);
        }
    }
}

// ---------------- out = attn @ out_w^T + out_b (3-pass bf16) ----------------
__global__ __launch_bounds__(256, 2) void out_proj_kernel(const float* __restrict__ W,
                                                          const float* __restrict__ bias,
                                                          float* __restrict__ out) {
    __shared__ __nv_bfloat16 Ah[2][128][LDA], Al[2][128][LDA], Bh[2][128][LDA], Bl[2][128][LDA];
    const int row0 = blockIdx.y * 128;
    const int col0 = blockIdx.x * 128;
    float acc[4][4][4] = {};
    gemm_main(g_attn + (size_t)row0 * E_, E_, W + (size_t)col0 * E_, E_, E_,
              Ah, Al, Bh, Bl, acc);
    const int lane = threadIdx.x & 31, warp = threadIdx.x >> 5;
    const int wm = warp >> 2, wn = warp & 3;
    const int gid = lane >> 2, t4 = lane & 3;
    #pragma unroll
    for (int mi = 0; mi < 4; mi++) {
        #pragma unroll
        for (int ni = 0; ni < 4; ni++) {
            int r = row0 + wm * 64 + mi * 16 + gid;
            int f = col0 + wn * 32 + ni * 8 + 2 * t4;
            float bb0 = bias[f], bb1 = bias[f + 1];
            *(float2*)&out[(size_t)r * E_ + f] =
                make_float2(acc[mi][ni][0] + bb0, acc[mi][ni][1] + bb1);
            *(float2*)&out[(size_t)(r + 8) * E_ + f] =
                make_float2(acc[mi][ni][2] + bb0, acc[mi][ni][3] + bb1);
        }
    }
}

// ---------------- launch ----------------
extern "C" void kernel_launch(void* const* d_in, const int* in_sizes, int n_in,
                              void* d_out, int out_size) {
    const float* fwd  = (const float*)d_in[0];
    const float* bwd  = (const float*)d_in[1];
    const int*   kpm  = (const int*)d_in[2];
    const float* W    = (const float*)d_in[3];   // (3E, E)
    const float* bias = (const float*)d_in[4];   // (3E,)
    const float* outw = (const float*)d_in[5];   // (E, E)
    const float* outb = (const float*)d_in[6];   // (E,)
    float* out = (float*)d_out;                       // (T,B,E)
    float* avg = out + (size_t)T_ * B_ * E_;          // (B,T,S)

    cudaFuncSetAttribute(scores_kernel,
                         cudaFuncAttributeMaxDynamicSharedMemorySize, SC_SMEM);

    build_qin_kernel<<<(T_ * B_ * E_) / 1024, 256>>>(fwd, bwd);
    proj_q_kernel<<<dim3(E_ / 128, (T_ * B_) / 128), 256>>>(W, bias);
    proj_kv_kernel<<<dim3((2 * E_) / 128, (S_ * B_) / 128), 256>>>(fwd, bwd, W, bias);
    scores_kernel<<<dim3(9, T_ / 128, B_ * H_), 256, SC_SMEM>>>();
    softmax_avg_kernel<<<B_ * T_, 256>>>(kpm, avg);
    attn_kernel<<<dim3(T_ / 128, B_ * H_), 256>>>();
    out_proj_kernel<<<dim3(E_ / 128, (T_ * B_) / 128), 256>>>(outw, outb, out);
}